// round 13
// baseline (speedup 1.0000x reference)
#include <cuda_runtime.h>
#include <cuda_bf16.h>
#include <cuda_fp16.h>

// ---------------- problem constants ----------------
#define BATCH   64
#define T_IN    8192
#define T2      4096        // after pool1
#define T4      2048        // after pool2
#define N_NODES 131072      // BATCH * T4
#define N_EDGES 2097152
#define HID     64
#define OUTC    10

typedef unsigned long long u64;

// ---------------- f32x2 packed helpers (Blackwell) ----------------
__device__ __forceinline__ u64 pk2(float lo, float hi) {
    u64 r; asm("mov.b64 %0, {%1, %2};" : "=l"(r) : "f"(lo), "f"(hi)); return r;
}
__device__ __forceinline__ void upk2(u64 v, float& lo, float& hi) {
    asm("mov.b64 {%0, %1}, %2;" : "=f"(lo), "=f"(hi) : "l"(v));
}
__device__ __forceinline__ void fma2(u64& acc, u64 a, u64 b) {
    asm("fma.rn.f32x2 %0, %1, %2, %3;" : "=l"(acc) : "l"(a), "l"(b), "l"(acc));
}

// ---------------- scratch (device globals, no allocation) ----------------
// NOTE: referenced ONLY inside device code (GB300 ATS silently reads the host
// shadow if passed as host-side kernel args).
__device__ __half2 g_feat_h[N_NODES * 16];       // conv2 out, UNscaled, fp16
__device__ float   g_z[N_NODES * 32];            // aggregated 32-dim features (fp32)
__device__ __half2 g_y_h[N_NODES * 32];          // dis * (relu(z@W1+b1) @ W2), fp16
__device__ float   g_pool[BATCH * 64];           // per-batch channel sums
__device__ float   g_dis[N_NODES];
__device__ int     g_cnt[N_NODES];
__device__ int     g_off[N_NODES + 1];
__device__ int     g_cur[N_NODES];
__device__ int     g_srcs[N_EDGES];
__device__ int     g_bsum[128];

// ---------------- fused conv1+conv2+pools -> fp16 node features (UNscaled) ----
// fp16 x tile in shared (4 blocks/SM); no CSR dependency -> launches at t=0.
#define SXH_W  264          // half2 words per channel row (262 valid + pad)
#define SXH_V  262          // 524 floats = 262 half2
#define SH1_W  264
#define SH1_V  260
#define SW1_N  (8 * 16 * 6)
#define SW2_N  (16 * 16 * 6)
#define SM_BYTES  (16*SXH_W*4 + 16*SH1_W*4 + (16+32)*4 + (SW1_N + SW2_N)*8)

__global__ void __launch_bounds__(256, 4)
conv_fused_kernel(const float* __restrict__ x,
                  const float* __restrict__ w1,
                  const float* __restrict__ b1,
                  const float* __restrict__ w2,
                  const float* __restrict__ b2) {
    extern __shared__ float sm[];
    __half2* sxh = (__half2*)sm;                     // [16][SXH_W]
    float*   sh1 = sm + 16 * SXH_W;                  // [16][SH1_W]
    float*   sb1 = sh1 + 16 * SH1_W;                 // [16]
    float*   sb2 = sb1 + 16;                         // [32]
    u64*     sw1 = (u64*)(sb2 + 32);                 // [SW1_N] stride-6 padded
    u64*     sw2 = sw1 + SW1_N;                      // [SW2_N]
    __half2* so  = (__half2*)sm;                     // ALIASES sxh (dead in phase 2)

    const int tile = blockIdx.x, bb = blockIdx.y, tid = threadIdx.x;

    // ---- loads ----
    const int x0 = tile * 512 - 6;                   // element offset of window base
    for (int i = tid; i < 16 * SXH_V; i += 256) {
        int ci = i / SXH_V, jh = i - ci * SXH_V;     // half2 word jh = elements 2jh, 2jh+1
        int t0e = x0 + 2 * jh;
        const float* xr = x + (size_t)(bb * 16 + ci) * T_IN;
        float a = (t0e >= 0 && t0e < T_IN) ? xr[t0e] : 0.f;
        float b = (t0e + 1 >= 0 && t0e + 1 < T_IN) ? xr[t0e + 1] : 0.f;
        sxh[ci * SXH_W + jh] = __floats2half2_rn(a, b);
    }
    for (int i = tid; i < 8 * 16 * 5; i += 256) {
        int cp = i / 80, r = i - cp * 80;            // r = ci*5 + k
        int ci = r / 5, k = r - ci * 5;
        sw1[(cp * 16 + ci) * 6 + k] = pk2(w1[(2 * cp) * 80 + r], w1[(2 * cp + 1) * 80 + r]);
    }
    for (int i = tid; i < 16 * 16 * 5; i += 256) {
        int cp = i / 80, r = i - cp * 80;
        int ci = r / 5, k = r - ci * 5;
        sw2[(cp * 16 + ci) * 6 + k] = pk2(w2[(2 * cp) * 80 + r], w2[(2 * cp + 1) * 80 + r]);
    }
    if (tid < 16) sb1[tid] = b1[tid];
    else if (tid < 48) sb2[tid - 16] = b2[tid - 16];
    __syncthreads();

    // ---- phase 1: conv1 + relu + pool over the 260-wide halo tile ----
    const int q0 = tile * 256 - 2;
    for (int j = tid; j < SH1_V; j += 256) {
        const int q = q0 + j;
        if (q < 0 || q >= T2) {
#pragma unroll
            for (int co = 0; co < 16; co++) sh1[co * SH1_W + j] = 0.f;
            continue;
        }
        u64 a0[8], a1[8];
#pragma unroll
        for (int cp = 0; cp < 8; cp++) { a0[cp] = 0ull; a1[cp] = 0ull; }
#pragma unroll
        for (int ci = 0; ci < 16; ci++) {
            const __half2* sxp = &sxh[ci * SXH_W + j];   // elements 2j..2j+5
            float2 v01 = __half22float2(sxp[0]);
            float2 v23 = __half22float2(sxp[1]);
            float2 v45 = __half22float2(sxp[2]);
            u64 x0p = pk2(v01.x, v01.x), x1p = pk2(v01.y, v01.y), x2p = pk2(v23.x, v23.x);
            u64 x3p = pk2(v23.y, v23.y), x4p = pk2(v45.x, v45.x), x5p = pk2(v45.y, v45.y);
#pragma unroll
            for (int cp = 0; cp < 8; cp++) {
                const u64* wp = &sw1[(cp * 16 + ci) * 6];
                ulonglong2 wA = *(const ulonglong2*)wp;        // w0, w1
                ulonglong2 wB = *(const ulonglong2*)(wp + 2);  // w2, w3
                u64 w4 = wp[4];
                fma2(a0[cp], wA.x, x0p); fma2(a1[cp], wA.x, x1p);
                fma2(a0[cp], wA.y, x1p); fma2(a1[cp], wA.y, x2p);
                fma2(a0[cp], wB.x, x2p); fma2(a1[cp], wB.x, x3p);
                fma2(a0[cp], wB.y, x3p); fma2(a1[cp], wB.y, x4p);
                fma2(a0[cp], w4,   x4p); fma2(a1[cp], w4,   x5p);
            }
        }
#pragma unroll
        for (int cp = 0; cp < 8; cp++) {
            float e0, o0, e1, o1;
            upk2(a0[cp], e0, o0);
            upk2(a1[cp], e1, o1);
            sh1[(2 * cp) * SH1_W + j]     = fmaxf(fmaxf(e0, e1) + sb1[2 * cp], 0.f);
            sh1[(2 * cp + 1) * SH1_W + j] = fmaxf(fmaxf(o0, o1) + sb1[2 * cp + 1], 0.f);
        }
    }
    __syncthreads();   // sxh dead beyond this point; so reuses it

    // ---- phase 2: conv2 + relu + pool, fp16 transpose write (unscaled) ----
    const int tp  = tid & 127;
    const int cob = tid >> 7;
    const int p0  = 2 * tp;

    u64 acc0[8], acc1[8];
#pragma unroll
    for (int q = 0; q < 8; q++) { acc0[q] = 0ull; acc1[q] = 0ull; }

#pragma unroll
    for (int ci = 0; ci < 16; ci++) {
        const float2* shp = (const float2*)&sh1[ci * SH1_W + p0];
        float2 v01 = shp[0], v23 = shp[1], v45 = shp[2];
        u64 x0p = pk2(v01.x, v01.x), x1p = pk2(v01.y, v01.y), x2p = pk2(v23.x, v23.x);
        u64 x3p = pk2(v23.y, v23.y), x4p = pk2(v45.x, v45.x), x5p = pk2(v45.y, v45.y);
#pragma unroll
        for (int q = 0; q < 8; q++) {
            const u64* wp = &sw2[((cob * 8 + q) * 16 + ci) * 6];
            ulonglong2 wA = *(const ulonglong2*)wp;
            ulonglong2 wB = *(const ulonglong2*)(wp + 2);
            u64 w4 = wp[4];
            fma2(acc0[q], wA.x, x0p); fma2(acc1[q], wA.x, x1p);
            fma2(acc0[q], wA.y, x1p); fma2(acc1[q], wA.y, x2p);
            fma2(acc0[q], wB.x, x2p); fma2(acc1[q], wB.x, x3p);
            fma2(acc0[q], wB.y, x3p); fma2(acc1[q], wB.y, x4p);
            fma2(acc0[q], w4,   x4p); fma2(acc1[q], w4,   x5p);
        }
    }

    const int node_base = bb * T4 + tile * 128;
#pragma unroll
    for (int q = 0; q < 8; q++) {
        int cp = cob * 8 + q;
        float e0, o0, e1, o1;
        upk2(acc0[q], e0, o0);
        upk2(acc1[q], e1, o1);
        float re = fmaxf(fmaxf(e0, e1) + sb2[2 * cp], 0.f);
        float ro = fmaxf(fmaxf(o0, o1) + sb2[2 * cp + 1], 0.f);
        so[tp * 17 + cp] = __floats2half2_rn(re, ro);
    }
    __syncthreads();

    for (int i = tid; i < 128 * 16; i += 256) {
        int lp = i >> 4, c = i & 15;
        g_feat_h[(node_base + lp) * 16 + c] = so[lp * 17 + c];
    }
}

// ---------------- CSR build ----------------
__global__ void zero_cnt_kernel() {
    int i = blockIdx.x * blockDim.x + threadIdx.x;
    if (i < N_NODES) g_cnt[i] = 0;
    if (i < BATCH * 64) g_pool[i] = 0.f;
}

__global__ void hist_kernel(const int* __restrict__ col) {
    int e = blockIdx.x * blockDim.x + threadIdx.x;
    if (e < N_EDGES) atomicAdd(&g_cnt[col[e]], 1);
}

// scan1 also produces g_dis (counts already in registers)
__global__ void scan1_kernel() {
    __shared__ int ss[256];
    const int tid = threadIdx.x;
    const int base = blockIdx.x * 1024 + tid * 4;
    int v0 = g_cnt[base], v1 = g_cnt[base + 1], v2 = g_cnt[base + 2], v3 = g_cnt[base + 3];
    g_dis[base]     = rsqrtf((float)(v0 + 1));
    g_dis[base + 1] = rsqrtf((float)(v1 + 1));
    g_dis[base + 2] = rsqrtf((float)(v2 + 1));
    g_dis[base + 3] = rsqrtf((float)(v3 + 1));
    int tsum = v0 + v1 + v2 + v3;
    ss[tid] = tsum;
    __syncthreads();
    for (int d = 1; d < 256; d <<= 1) {
        int t = (tid >= d) ? ss[tid - d] : 0;
        __syncthreads();
        ss[tid] += t;
        __syncthreads();
    }
    int excl = ss[tid] - tsum;
    g_off[base]     = excl;
    g_off[base + 1] = excl + v0;
    g_off[base + 2] = excl + v0 + v1;
    g_off[base + 3] = excl + v0 + v1 + v2;
    if (tid == 255) g_bsum[blockIdx.x] = ss[255];
}

__global__ void scan2_kernel() {
    __shared__ int ss[128];
    const int tid = threadIdx.x;
    int v = g_bsum[tid];
    ss[tid] = v;
    __syncthreads();
    for (int d = 1; d < 128; d <<= 1) {
        int t = (tid >= d) ? ss[tid - d] : 0;
        __syncthreads();
        ss[tid] += t;
        __syncthreads();
    }
    g_bsum[tid] = ss[tid] - v;
}

__global__ void scan3_kernel() {
    int i = blockIdx.x * blockDim.x + threadIdx.x;
    if (i < N_NODES) {
        int o = g_off[i] + g_bsum[i >> 10];
        g_off[i] = o;
        g_cur[i] = o;
        if (i == 0) g_off[N_NODES] = N_EDGES;
    }
}

__global__ void place_kernel(const int* __restrict__ row, const int* __restrict__ col) {
    int e = blockIdx.x * blockDim.x + threadIdx.x;
    if (e < N_EDGES) {
        int c = col[e];
        int p = atomicAdd(&g_cur[c], 1);
        g_srcs[p] = row[e];
    }
}

// ---------------- gather32 (fp16, dis applied on the fly, fp32) -------------
// z[i] = dis_i * (dis_i*feat_i + sum_j dis_j*feat_j)
__global__ void gather32_kernel() {
    const int gw = (blockIdx.x * 256 + threadIdx.x) >> 5;
    const int lane = threadIdx.x & 31;
    const int hw = lane >> 4, c = lane & 15;
    const __half2* __restrict__ y = g_feat_h;

    float ax = 0.f, ay = 0.f;
    int p = g_off[gw];
    const int e = g_off[gw + 1];
    for (; p + 8 <= e; p += 8) {
        int j0 = __ldg(&g_srcs[p + 0 + hw]);
        int j1 = __ldg(&g_srcs[p + 2 + hw]);
        int j2 = __ldg(&g_srcs[p + 4 + hw]);
        int j3 = __ldg(&g_srcs[p + 6 + hw]);
        float d0 = __ldg(&g_dis[j0]), d1 = __ldg(&g_dis[j1]);
        float d2 = __ldg(&g_dis[j2]), d3 = __ldg(&g_dis[j3]);
        float2 v0 = __half22float2(__ldg(&y[j0 * 16 + c]));
        float2 v1 = __half22float2(__ldg(&y[j1 * 16 + c]));
        float2 v2 = __half22float2(__ldg(&y[j2 * 16 + c]));
        float2 v3 = __half22float2(__ldg(&y[j3 * 16 + c]));
        ax += (fmaf(d0, v0.x, d1 * v1.x)) + (fmaf(d2, v2.x, d3 * v3.x));
        ay += (fmaf(d0, v0.y, d1 * v1.y)) + (fmaf(d2, v2.y, d3 * v3.y));
    }
    for (; p + 2 <= e; p += 2) {
        int j = __ldg(&g_srcs[p + hw]);
        float d = __ldg(&g_dis[j]);
        float2 v = __half22float2(__ldg(&y[j * 16 + c]));
        ax = fmaf(d, v.x, ax); ay = fmaf(d, v.y, ay);
    }
    if (p < e && hw == 0) {
        int j = __ldg(&g_srcs[p]);
        float d = __ldg(&g_dis[j]);
        float2 v = __half22float2(__ldg(&y[j * 16 + c]));
        ax = fmaf(d, v.x, ax); ay = fmaf(d, v.y, ay);
    }
    ax += __shfl_xor_sync(0xFFFFFFFFu, ax, 16);
    ay += __shfl_xor_sync(0xFFFFFFFFu, ay, 16);
    if (lane < 16) {
        float2 self = __half22float2(__ldg(&y[gw * 16 + c]));
        const float di = g_dis[gw];
        float2 r;
        r.x = fmaf(di, self.x, ax) * di;
        r.y = fmaf(di, self.y, ay) * di;
        ((float2*)g_z)[gw * 16 + c] = r;
    }
}

// ---------------- fused GCN matmuls: y = dis * (relu(z@W1 + b1) @ W2), fp16 ----
__global__ void xw_fused_kernel(const float* __restrict__ W1,
                                const float* __restrict__ b1,
                                const float* __restrict__ W2) {
    __shared__ __align__(16) u64 sW1[32 * 32];
    __shared__ __align__(16) u64 sW2[64 * 32];
    __shared__ float sb1v[64];
    const int tid = threadIdx.x;
    for (int i = tid; i < 32 * 32; i += 256) {
        float2 wv = ((const float2*)W1)[i];
        sW1[i] = pk2(wv.x, wv.y);
    }
    for (int i = tid; i < 64 * 32; i += 256) {
        float2 wv = ((const float2*)W2)[i];
        sW2[i] = pk2(wv.x, wv.y);
    }
    if (tid < 64) sb1v[tid] = b1[tid];
    __syncthreads();

    const int n = blockIdx.x * 256 + tid;

    u64 acc1[32];
#pragma unroll
    for (int j = 0; j < 32; j++) acc1[j] = 0ull;
    const float4* fv = (const float4*)(g_z + (size_t)n * 32);
#pragma unroll
    for (int kc = 0; kc < 8; kc++) {
        float4 xv = fv[kc];
#pragma unroll
        for (int kk = 0; kk < 4; kk++) {
            float xk = (kk == 0) ? xv.x : (kk == 1) ? xv.y : (kk == 2) ? xv.z : xv.w;
            u64 x2 = pk2(xk, xk);
            const ulonglong2* wrow = (const ulonglong2*)&sW1[(kc * 4 + kk) * 32];
#pragma unroll
            for (int j = 0; j < 16; j++) {
                ulonglong2 wv = wrow[j];
                fma2(acc1[2 * j],     x2, wv.x);
                fma2(acc1[2 * j + 1], x2, wv.y);
            }
        }
    }

    u64 acc2[32];
#pragma unroll
    for (int j = 0; j < 32; j++) acc2[j] = 0ull;
#pragma unroll
    for (int j = 0; j < 32; j++) {
        float l, h;
        upk2(acc1[j], l, h);
        l = fmaxf(l + sb1v[2 * j], 0.f);
        h = fmaxf(h + sb1v[2 * j + 1], 0.f);
        u64 xl = pk2(l, l), xh = pk2(h, h);
        const ulonglong2* r0 = (const ulonglong2*)&sW2[(2 * j) * 32];
        const ulonglong2* r1 = (const ulonglong2*)&sW2[(2 * j + 1) * 32];
#pragma unroll
        for (int m = 0; m < 16; m++) {
            ulonglong2 wa = r0[m];
            fma2(acc2[2 * m],     xl, wa.x);
            fma2(acc2[2 * m + 1], xl, wa.y);
            ulonglong2 wb = r1[m];
            fma2(acc2[2 * m],     xh, wb.x);
            fma2(acc2[2 * m + 1], xh, wb.y);
        }
    }

    const float di = g_dis[n];
    __half2* o = g_y_h + (size_t)n * 32;
#pragma unroll
    for (int q = 0; q < 8; q++) {
        float l0, h0, l1, h1, l2, h2, l3, h3;
        upk2(acc2[4 * q + 0], l0, h0);
        upk2(acc2[4 * q + 1], l1, h1);
        upk2(acc2[4 * q + 2], l2, h2);
        upk2(acc2[4 * q + 3], l3, h3);
        __half2 a = __floats2half2_rn(l0 * di, h0 * di);
        __half2 b = __floats2half2_rn(l1 * di, h1 * di);
        __half2 cc = __floats2half2_rn(l2 * di, h2 * di);
        __half2 dd = __floats2half2_rn(l3 * di, h3 * di);
        uint4 pack;
        pack.x = *(unsigned*)&a;  pack.y = *(unsigned*)&b;
        pack.z = *(unsigned*)&cc; pack.w = *(unsigned*)&dd;
        ((uint4*)o)[q] = pack;
    }
}

// ---------------- gather64 + fused mean-pool partial reduction ----------------
__global__ void gather64_pool_kernel(const float* __restrict__ bias) {
    __shared__ float pool[64];
    const __half2* __restrict__ y = g_y_h;
    const int tid = threadIdx.x;
    const int gw = (blockIdx.x * 256 + tid) >> 5;
    const int lane = tid & 31;
    if (tid < 64) pool[tid] = 0.f;
    __syncthreads();

    float2 a = __half22float2(__ldg(&y[gw * 32 + lane]));
    int p = g_off[gw];
    const int e = g_off[gw + 1];
    for (; p + 8 <= e; p += 8) {
        int j0 = __ldg(&g_srcs[p + 0]), j1 = __ldg(&g_srcs[p + 1]);
        int j2 = __ldg(&g_srcs[p + 2]), j3 = __ldg(&g_srcs[p + 3]);
        int j4 = __ldg(&g_srcs[p + 4]), j5 = __ldg(&g_srcs[p + 5]);
        int j6 = __ldg(&g_srcs[p + 6]), j7 = __ldg(&g_srcs[p + 7]);
        float2 v0 = __half22float2(__ldg(&y[j0 * 32 + lane]));
        float2 v1 = __half22float2(__ldg(&y[j1 * 32 + lane]));
        float2 v2 = __half22float2(__ldg(&y[j2 * 32 + lane]));
        float2 v3 = __half22float2(__ldg(&y[j3 * 32 + lane]));
        float2 v4 = __half22float2(__ldg(&y[j4 * 32 + lane]));
        float2 v5 = __half22float2(__ldg(&y[j5 * 32 + lane]));
        float2 v6 = __half22float2(__ldg(&y[j6 * 32 + lane]));
        float2 v7 = __half22float2(__ldg(&y[j7 * 32 + lane]));
        a.x += ((v0.x + v1.x) + (v2.x + v3.x)) + ((v4.x + v5.x) + (v6.x + v7.x));
        a.y += ((v0.y + v1.y) + (v2.y + v3.y)) + ((v4.y + v5.y) + (v6.y + v7.y));
    }
    for (; p < e; p++) {
        int j = __ldg(&g_srcs[p]);
        float2 v = __half22float2(__ldg(&y[j * 32 + lane]));
        a.x += v.x; a.y += v.y;
    }
    const float d = g_dis[gw];
    float2 bb = ((const float2*)bias)[lane];
    float rx = fmaxf(fmaf(d, a.x, bb.x), 0.f);
    float ry = fmaxf(fmaf(d, a.y, bb.y), 0.f);
    atomicAdd(&pool[2 * lane],     rx);
    atomicAdd(&pool[2 * lane + 1], ry);
    __syncthreads();
    if (tid < 64) {
        const int batch = gw >> 11;      // 2048 nodes per batch; 8 nodes/block aligned
        atomicAdd(&g_pool[batch * 64 + tid], pool[tid]);
    }
}

// ---------------- classifier from pooled sums ----------------
__global__ void cls_kernel(const float* __restrict__ clsw,
                           const float* __restrict__ clsb,
                           float* __restrict__ out) {
    __shared__ float sw[64 * OUTC];
    const int tid = threadIdx.x;
    if (tid < 64 * OUTC) sw[tid] = clsw[tid];
    __syncthreads();
    if (tid < BATCH * OUTC) {
        const int b = tid / OUTC, o = tid - b * OUTC;
        float acc = clsb[o];
#pragma unroll
        for (int c = 0; c < 64; c++)
            acc += g_pool[b * 64 + c] * sw[c * OUTC + o];
        out[tid] = acc * (1.f / (float)T4) + clsb[o] * (1.f - 1.f / (float)T4);
    }
}

// ---------------- launch ----------------
extern "C" void kernel_launch(void* const* d_in, const int* in_sizes, int n_in,
                              void* d_out, int out_size) {
    const float* x       = nullptr;
    const int*   ei      = nullptr;
    const float* conv1_w = nullptr; const float* conv1_b = nullptr;
    const float* conv2_w = nullptr; const float* conv2_b = nullptr;
    const float* gcn1_w  = nullptr; const float* gcn1_b  = nullptr;
    const float* gcn2_w  = nullptr; const float* gcn2_b  = nullptr;
    const float* cls_w   = nullptr; const float* cls_b   = nullptr;

    for (int i = 0; i < n_in; i++) {
        switch (in_sizes[i]) {
            case BATCH * 16 * T_IN:   x       = (const float*)d_in[i]; break;
            case 2 * N_EDGES:         ei      = (const int*)  d_in[i]; break;
            case 16 * 16 * 5:         conv1_w = (const float*)d_in[i]; break;
            case 16:                  conv1_b = (const float*)d_in[i]; break;
            case 32 * 16 * 5:         conv2_w = (const float*)d_in[i]; break;
            case 32:                  conv2_b = (const float*)d_in[i]; break;
            case 32 * HID:            gcn1_w  = (const float*)d_in[i]; break;
            case HID * HID:           gcn2_w  = (const float*)d_in[i]; break;
            case HID * OUTC:          cls_w   = (const float*)d_in[i]; break;
            case OUTC:                cls_b   = (const float*)d_in[i]; break;
            case HID:
                if (!gcn1_b) gcn1_b = (const float*)d_in[i];
                else         gcn2_b = (const float*)d_in[i];
                break;
            default: break;
        }
    }
    if (!x || !ei || !conv1_w || !conv2_w || !gcn1_w || !gcn2_w || !cls_w) {
        x       = (const float*)d_in[0];  ei      = (const int*)  d_in[1];
        conv1_w = (const float*)d_in[2];  conv1_b = (const float*)d_in[3];
        conv2_w = (const float*)d_in[4];  conv2_b = (const float*)d_in[5];
        gcn1_w  = (const float*)d_in[6];  gcn1_b  = (const float*)d_in[7];
        gcn2_w  = (const float*)d_in[8];  gcn2_b  = (const float*)d_in[9];
        cls_w   = (const float*)d_in[10]; cls_b   = (const float*)d_in[11];
    }

    float* out = (float*)d_out;
    const int* e_row = ei;
    const int* e_col = ei + N_EDGES;

    cudaFuncSetAttribute(conv_fused_kernel,
                         cudaFuncAttributeMaxDynamicSharedMemorySize, SM_BYTES);

    // Side stream + events, created once (no device-memory alloc; identical
    // launch graph every call).
    static cudaStream_t s_side = nullptr;
    static cudaEvent_t  s_fork = nullptr, s_csr = nullptr;
    if (!s_side) {
        cudaStreamCreateWithFlags(&s_side, cudaStreamNonBlocking);
        cudaEventCreateWithFlags(&s_fork, cudaEventDisableTiming);
        cudaEventCreateWithFlags(&s_csr,  cudaEventDisableTiming);
    }

    // fork at t=0: ENTIRE CSR build runs beside conv_fused (conv is
    // CSR-independent now; dis is applied inside gather32 in fp32)
    cudaEventRecord(s_fork, 0);
    cudaStreamWaitEvent(s_side, s_fork, 0);
    zero_cnt_kernel<<<N_NODES / 256, 256, 0, s_side>>>();
    hist_kernel<<<N_EDGES / 256, 256, 0, s_side>>>(e_col);
    scan1_kernel<<<128, 256, 0, s_side>>>();            // also computes g_dis
    scan2_kernel<<<1, 128, 0, s_side>>>();
    scan3_kernel<<<N_NODES / 256, 256, 0, s_side>>>();
    place_kernel<<<N_EDGES / 256, 256, 0, s_side>>>(e_row, e_col);
    cudaEventRecord(s_csr, s_side);

    // main stream: conv starts at t=0
    {
        dim3 gc(T4 / 128, BATCH);
        conv_fused_kernel<<<gc, 256, SM_BYTES>>>(x, conv1_w, conv1_b, conv2_w, conv2_b);
    }

    // join: gather32 needs conv output + full CSR + dis
    cudaStreamWaitEvent(0, s_csr, 0);
    gather32_kernel<<<N_NODES / 8, 256>>>();
    xw_fused_kernel<<<N_NODES / 256, 256>>>(gcn1_w, gcn1_b, gcn2_w);
    gather64_pool_kernel<<<N_NODES / 8, 256>>>(gcn2_b);
    cls_kernel<<<1, 640>>>(cls_w, cls_b, out);
}

// round 14
// speedup vs baseline: 1.2233x; 1.2233x over previous
#include <cuda_runtime.h>
#include <cuda_bf16.h>
#include <cuda_fp16.h>

// ---------------- problem constants ----------------
#define BATCH   64
#define T_IN    8192
#define T2      4096        // after pool1
#define T4      2048        // after pool2
#define N_NODES 131072      // BATCH * T4
#define N_EDGES 2097152
#define HID     64
#define OUTC    10

typedef unsigned long long u64;

// ---------------- f32x2 packed helpers (Blackwell) ----------------
__device__ __forceinline__ u64 pk2(float lo, float hi) {
    u64 r; asm("mov.b64 %0, {%1, %2};" : "=l"(r) : "f"(lo), "f"(hi)); return r;
}
__device__ __forceinline__ void upk2(u64 v, float& lo, float& hi) {
    asm("mov.b64 {%0, %1}, %2;" : "=f"(lo), "=f"(hi) : "l"(v));
}
__device__ __forceinline__ void fma2(u64& acc, u64 a, u64 b) {
    asm("fma.rn.f32x2 %0, %1, %2, %3;" : "=l"(acc) : "l"(a), "l"(b), "l"(acc));
}

// m16n8k16 fp16 MMA, fp32 accumulate (HMMA)
__device__ __forceinline__ void mma16816(float* d, const unsigned* a, const unsigned* b) {
    asm volatile(
        "mma.sync.aligned.m16n8k16.row.col.f32.f16.f16.f32 "
        "{%0,%1,%2,%3}, {%4,%5,%6,%7}, {%8,%9}, {%0,%1,%2,%3};"
        : "+f"(d[0]), "+f"(d[1]), "+f"(d[2]), "+f"(d[3])
        : "r"(a[0]), "r"(a[1]), "r"(a[2]), "r"(a[3]), "r"(b[0]), "r"(b[1]));
}

// ---------------- scratch (device globals, no allocation) ----------------
// NOTE: referenced ONLY inside device code (GB300 ATS silently reads the host
// shadow if passed as host-side kernel args).
__device__ __half2 g_feat_h[N_NODES * 16];       // conv2 out * dis, fp16, node-major
__device__ float   g_z[N_NODES * 32];            // aggregated 32-dim features (fp32)
__device__ __half2 g_y_h[N_NODES * 32];          // dis * (relu(z@W1+b1) @ W2), fp16
__device__ float   g_pool[BATCH * 64];           // per-batch channel sums
__device__ float   g_dis[N_NODES];
__device__ int     g_cnt[N_NODES];
__device__ int     g_off[N_NODES + 1];
__device__ int     g_cur[N_NODES];
__device__ int     g_srcs[N_EDGES];
__device__ int     g_bsum[128];

// ---------------- fused conv1+conv2+pools+dis -> fp16 node features ----------
// (R8/R10 version: fp32 sx, so-aliases-sx, 68 regs, 3 blocks/SM.)
#define SX_W   528
#define SX_V   524
#define SH1_W  264
#define SH1_V  260
#define SW1_N  (8 * 16 * 6)
#define SW2_N  (16 * 16 * 6)
#define SM_FLOATS (16*SX_W + 16*SH1_W + 16 + 32)
#define SM_BYTES  (SM_FLOATS*4 + (SW1_N + SW2_N)*8)

__global__ void conv_fused_kernel(const float* __restrict__ x,
                                  const float* __restrict__ w1,
                                  const float* __restrict__ b1,
                                  const float* __restrict__ w2,
                                  const float* __restrict__ b2) {
    extern __shared__ float sm[];
    float*   sx  = sm;                       // [16][SX_W]
    float*   sh1 = sm + 16 * SX_W;           // [16][SH1_W]
    float*   sb1 = sh1 + 16 * SH1_W;         // [16]
    float*   sb2 = sb1 + 16;                 // [32]
    u64*     sw1 = (u64*)(sb2 + 32);         // [SW1_N] stride-6 padded
    u64*     sw2 = sw1 + SW1_N;              // [SW2_N]
    __half2* so  = (__half2*)sm;             // ALIASES sx (dead in phase 2)

    const int tile = blockIdx.x, bb = blockIdx.y, tid = threadIdx.x;

    const int x0 = tile * 512 - 6;
    for (int i = tid; i < 16 * SX_V; i += 256) {
        int ci = i / SX_V, j = i - ci * SX_V;
        int t = x0 + j;
        sx[ci * SX_W + j] = (t >= 0 && t < T_IN) ? x[(bb * 16 + ci) * T_IN + t] : 0.f;
    }
    for (int i = tid; i < 8 * 16 * 5; i += 256) {
        int cp = i / 80, r = i - cp * 80;
        int ci = r / 5, k = r - ci * 5;
        sw1[(cp * 16 + ci) * 6 + k] = pk2(w1[(2 * cp) * 80 + r], w1[(2 * cp + 1) * 80 + r]);
    }
    for (int i = tid; i < 16 * 16 * 5; i += 256) {
        int cp = i / 80, r = i - cp * 80;
        int ci = r / 5, k = r - ci * 5;
        sw2[(cp * 16 + ci) * 6 + k] = pk2(w2[(2 * cp) * 80 + r], w2[(2 * cp + 1) * 80 + r]);
    }
    if (tid < 16) sb1[tid] = b1[tid];
    else if (tid < 48) sb2[tid - 16] = b2[tid - 16];
    __syncthreads();

    const int q0 = tile * 256 - 2;
    for (int j = tid; j < SH1_V; j += 256) {
        const int q = q0 + j;
        if (q < 0 || q >= T2) {
#pragma unroll
            for (int co = 0; co < 16; co++) sh1[co * SH1_W + j] = 0.f;
            continue;
        }
        const int px = 2 * j;
        u64 a0[8], a1[8];
#pragma unroll
        for (int cp = 0; cp < 8; cp++) { a0[cp] = 0ull; a1[cp] = 0ull; }
#pragma unroll
        for (int ci = 0; ci < 16; ci++) {
            const float2* sxp = (const float2*)&sx[ci * SX_W + px];
            float2 v01 = sxp[0], v23 = sxp[1], v45 = sxp[2];
            u64 x0p = pk2(v01.x, v01.x), x1p = pk2(v01.y, v01.y), x2p = pk2(v23.x, v23.x);
            u64 x3p = pk2(v23.y, v23.y), x4p = pk2(v45.x, v45.x), x5p = pk2(v45.y, v45.y);
#pragma unroll
            for (int cp = 0; cp < 8; cp++) {
                const u64* wp = &sw1[(cp * 16 + ci) * 6];
                ulonglong2 wA = *(const ulonglong2*)wp;
                ulonglong2 wB = *(const ulonglong2*)(wp + 2);
                u64 w4 = wp[4];
                fma2(a0[cp], wA.x, x0p); fma2(a1[cp], wA.x, x1p);
                fma2(a0[cp], wA.y, x1p); fma2(a1[cp], wA.y, x2p);
                fma2(a0[cp], wB.x, x2p); fma2(a1[cp], wB.x, x3p);
                fma2(a0[cp], wB.y, x3p); fma2(a1[cp], wB.y, x4p);
                fma2(a0[cp], w4,   x4p); fma2(a1[cp], w4,   x5p);
            }
        }
#pragma unroll
        for (int cp = 0; cp < 8; cp++) {
            float e0, o0, e1, o1;
            upk2(a0[cp], e0, o0);
            upk2(a1[cp], e1, o1);
            sh1[(2 * cp) * SH1_W + j]     = fmaxf(fmaxf(e0, e1) + sb1[2 * cp], 0.f);
            sh1[(2 * cp + 1) * SH1_W + j] = fmaxf(fmaxf(o0, o1) + sb1[2 * cp + 1], 0.f);
        }
    }
    __syncthreads();

    const int tp  = tid & 127;
    const int cob = tid >> 7;
    const int p0  = 2 * tp;

    u64 acc0[8], acc1[8];
#pragma unroll
    for (int q = 0; q < 8; q++) { acc0[q] = 0ull; acc1[q] = 0ull; }

#pragma unroll
    for (int ci = 0; ci < 16; ci++) {
        const float2* shp = (const float2*)&sh1[ci * SH1_W + p0];
        float2 v01 = shp[0], v23 = shp[1], v45 = shp[2];
        u64 x0p = pk2(v01.x, v01.x), x1p = pk2(v01.y, v01.y), x2p = pk2(v23.x, v23.x);
        u64 x3p = pk2(v23.y, v23.y), x4p = pk2(v45.x, v45.x), x5p = pk2(v45.y, v45.y);
#pragma unroll
        for (int q = 0; q < 8; q++) {
            const u64* wp = &sw2[((cob * 8 + q) * 16 + ci) * 6];
            ulonglong2 wA = *(const ulonglong2*)wp;
            ulonglong2 wB = *(const ulonglong2*)(wp + 2);
            u64 w4 = wp[4];
            fma2(acc0[q], wA.x, x0p); fma2(acc1[q], wA.x, x1p);
            fma2(acc0[q], wA.y, x1p); fma2(acc1[q], wA.y, x2p);
            fma2(acc0[q], wB.x, x2p); fma2(acc1[q], wB.x, x3p);
            fma2(acc0[q], wB.y, x3p); fma2(acc1[q], wB.y, x4p);
            fma2(acc0[q], w4,   x4p); fma2(acc1[q], w4,   x5p);
        }
    }

    const int node_base = bb * T4 + tile * 128;
    const float d = __ldg(&g_dis[node_base + tp]);
#pragma unroll
    for (int q = 0; q < 8; q++) {
        int cp = cob * 8 + q;
        float e0, o0, e1, o1;
        upk2(acc0[q], e0, o0);
        upk2(acc1[q], e1, o1);
        float re = fmaxf(fmaxf(e0, e1) + sb2[2 * cp], 0.f) * d;
        float ro = fmaxf(fmaxf(o0, o1) + sb2[2 * cp + 1], 0.f) * d;
        so[tp * 17 + cp] = __floats2half2_rn(re, ro);
    }
    __syncthreads();

    for (int i = tid; i < 128 * 16; i += 256) {
        int lp = i >> 4, c = i & 15;
        g_feat_h[(node_base + lp) * 16 + c] = so[lp * 17 + c];
    }
}

// ---------------- CSR build ----------------
__global__ void zero_cnt_kernel() {
    int i = blockIdx.x * blockDim.x + threadIdx.x;
    if (i < N_NODES) g_cnt[i] = 0;
    if (i < BATCH * 64) g_pool[i] = 0.f;
}

__global__ void hist_kernel(const int* __restrict__ col) {
    int e = blockIdx.x * blockDim.x + threadIdx.x;
    if (e < N_EDGES) atomicAdd(&g_cnt[col[e]], 1);
}

__global__ void scan1_kernel() {
    __shared__ int ss[256];
    const int tid = threadIdx.x;
    const int base = blockIdx.x * 1024 + tid * 4;
    int v0 = g_cnt[base], v1 = g_cnt[base + 1], v2 = g_cnt[base + 2], v3 = g_cnt[base + 3];
    g_dis[base]     = rsqrtf((float)(v0 + 1));
    g_dis[base + 1] = rsqrtf((float)(v1 + 1));
    g_dis[base + 2] = rsqrtf((float)(v2 + 1));
    g_dis[base + 3] = rsqrtf((float)(v3 + 1));
    int tsum = v0 + v1 + v2 + v3;
    ss[tid] = tsum;
    __syncthreads();
    for (int d = 1; d < 256; d <<= 1) {
        int t = (tid >= d) ? ss[tid - d] : 0;
        __syncthreads();
        ss[tid] += t;
        __syncthreads();
    }
    int excl = ss[tid] - tsum;
    g_off[base]     = excl;
    g_off[base + 1] = excl + v0;
    g_off[base + 2] = excl + v0 + v1;
    g_off[base + 3] = excl + v0 + v1 + v2;
    if (tid == 255) g_bsum[blockIdx.x] = ss[255];
}

__global__ void scan2_kernel() {
    __shared__ int ss[128];
    const int tid = threadIdx.x;
    int v = g_bsum[tid];
    ss[tid] = v;
    __syncthreads();
    for (int d = 1; d < 128; d <<= 1) {
        int t = (tid >= d) ? ss[tid - d] : 0;
        __syncthreads();
        ss[tid] += t;
        __syncthreads();
    }
    g_bsum[tid] = ss[tid] - v;
}

__global__ void scan3_kernel() {
    int i = blockIdx.x * blockDim.x + threadIdx.x;
    if (i < N_NODES) {
        int o = g_off[i] + g_bsum[i >> 10];
        g_off[i] = o;
        g_cur[i] = o;
        if (i == 0) g_off[N_NODES] = N_EDGES;
    }
}

__global__ void place_kernel(const int* __restrict__ row, const int* __restrict__ col) {
    int e = blockIdx.x * blockDim.x + threadIdx.x;
    if (e < N_EDGES) {
        int c = col[e];
        int p = atomicAdd(&g_cur[c], 1);
        g_srcs[p] = row[e];
    }
}

// ---------------- gather32 (fp16): z[i] = dis_i * (feat~[i] + sum feat~[j]) ----
__global__ void gather32_kernel() {
    const int gw = (blockIdx.x * 256 + threadIdx.x) >> 5;
    const int lane = threadIdx.x & 31;
    const int hw = lane >> 4, c = lane & 15;
    const __half2* __restrict__ y = g_feat_h;

    float ax = 0.f, ay = 0.f;
    int p = g_off[gw];
    const int e = g_off[gw + 1];
    for (; p + 8 <= e; p += 8) {
        int j0 = __ldg(&g_srcs[p + 0 + hw]);
        int j1 = __ldg(&g_srcs[p + 2 + hw]);
        int j2 = __ldg(&g_srcs[p + 4 + hw]);
        int j3 = __ldg(&g_srcs[p + 6 + hw]);
        float2 v0 = __half22float2(__ldg(&y[j0 * 16 + c]));
        float2 v1 = __half22float2(__ldg(&y[j1 * 16 + c]));
        float2 v2 = __half22float2(__ldg(&y[j2 * 16 + c]));
        float2 v3 = __half22float2(__ldg(&y[j3 * 16 + c]));
        ax += (v0.x + v1.x) + (v2.x + v3.x);
        ay += (v0.y + v1.y) + (v2.y + v3.y);
    }
    for (; p + 2 <= e; p += 2) {
        int j = __ldg(&g_srcs[p + hw]);
        float2 v = __half22float2(__ldg(&y[j * 16 + c]));
        ax += v.x; ay += v.y;
    }
    if (p < e && hw == 0) {
        int j = __ldg(&g_srcs[p]);
        float2 v = __half22float2(__ldg(&y[j * 16 + c]));
        ax += v.x; ay += v.y;
    }
    ax += __shfl_xor_sync(0xFFFFFFFFu, ax, 16);
    ay += __shfl_xor_sync(0xFFFFFFFFu, ay, 16);
    if (lane < 16) {
        float2 self = __half22float2(__ldg(&y[gw * 16 + c]));
        const float d = g_dis[gw];
        float2 r;
        r.x = (self.x + ax) * d;
        r.y = (self.y + ay) * d;
        ((float2*)g_z)[gw * 16 + c] = r;
    }
}

// ---------------- xw via tensor cores (HMMA m16n8k16) ------------------------
// y = dis * (relu(z@W1 + b1) @ W2), fp16 out. One warp = 16 nodes.
// Weights pre-transposed in shared ([n][k], padded) so B-fragments are single
// aligned half2 loads; h staged per-warp in padded shared for stage-2 A-frags.
__global__ void __launch_bounds__(256)
xw_mma_kernel(const float* __restrict__ W1,
              const float* __restrict__ b1,
              const float* __restrict__ W2) {
    __shared__ __align__(16) __half sW1t[64 * 40];   // [n][k], stride 40
    __shared__ __align__(16) __half sW2t[64 * 72];   // [n][k], stride 72
    __shared__ float sb1v[64];
    __shared__ __align__(16) __half sH[8][16 * 72];  // per-warp h, row stride 72

    const int tid = threadIdx.x;
    for (int i = tid; i < 32 * 64; i += 256) {
        int k = i >> 6, n = i & 63;
        sW1t[n * 40 + k] = __float2half_rn(W1[i]);
    }
    for (int i = tid; i < 64 * 64; i += 256) {
        int k = i >> 6, n = i & 63;
        sW2t[n * 72 + k] = __float2half_rn(W2[i]);
    }
    if (tid < 64) sb1v[tid] = b1[tid];
    __syncthreads();

    const int w = tid >> 5, lane = tid & 31;
    const int g = lane >> 2, t = lane & 3;
    const int nb = blockIdx.x * 128 + w * 16;
    __half* H = &sH[w][0];

    // ---- stage 1: C1[16x64] = A(z)[16x32] @ W1[32x64] ----
    float acc[8][4];
#pragma unroll
    for (int nf = 0; nf < 8; nf++)
#pragma unroll
        for (int q = 0; q < 4; q++) acc[nf][q] = 0.f;

#pragma unroll
    for (int kf = 0; kf < 2; kf++) {
        const int k0 = kf * 16;
        unsigned a[4];
        {
            float2 v;
            v = *(const float2*)&g_z[(size_t)(nb + g) * 32 + k0 + 2 * t];
            __half2 h = __floats2half2_rn(v.x, v.y); a[0] = *(unsigned*)&h;
            v = *(const float2*)&g_z[(size_t)(nb + g + 8) * 32 + k0 + 2 * t];
            h = __floats2half2_rn(v.x, v.y); a[1] = *(unsigned*)&h;
            v = *(const float2*)&g_z[(size_t)(nb + g) * 32 + k0 + 2 * t + 8];
            h = __floats2half2_rn(v.x, v.y); a[2] = *(unsigned*)&h;
            v = *(const float2*)&g_z[(size_t)(nb + g + 8) * 32 + k0 + 2 * t + 8];
            h = __floats2half2_rn(v.x, v.y); a[3] = *(unsigned*)&h;
        }
#pragma unroll
        for (int nf = 0; nf < 8; nf++) {
            unsigned b[2];
            b[0] = *(const unsigned*)&sW1t[(nf * 8 + g) * 40 + k0 + 2 * t];
            b[1] = *(const unsigned*)&sW1t[(nf * 8 + g) * 40 + k0 + 2 * t + 8];
            mma16816(acc[nf], a, b);
        }
    }

    // ---- bias + relu -> fp16 staging ----
#pragma unroll
    for (int nf = 0; nf < 8; nf++) {
        const int c0 = nf * 8 + 2 * t;
        float h0 = fmaxf(acc[nf][0] + sb1v[c0],     0.f);
        float h1 = fmaxf(acc[nf][1] + sb1v[c0 + 1], 0.f);
        float h2 = fmaxf(acc[nf][2] + sb1v[c0],     0.f);
        float h3 = fmaxf(acc[nf][3] + sb1v[c0 + 1], 0.f);
        *(__half2*)&H[g * 72 + c0]       = __floats2half2_rn(h0, h1);
        *(__half2*)&H[(g + 8) * 72 + c0] = __floats2half2_rn(h2, h3);
    }
    __syncwarp();

    // ---- stage 2: C2[16x64] = h[16x64] @ W2[64x64] ----
    float acc2[8][4];
#pragma unroll
    for (int nf = 0; nf < 8; nf++)
#pragma unroll
        for (int q = 0; q < 4; q++) acc2[nf][q] = 0.f;

#pragma unroll
    for (int kf = 0; kf < 4; kf++) {
        const int k0 = kf * 16;
        unsigned a[4];
        a[0] = *(const unsigned*)&H[g * 72 + k0 + 2 * t];
        a[1] = *(const unsigned*)&H[(g + 8) * 72 + k0 + 2 * t];
        a[2] = *(const unsigned*)&H[g * 72 + k0 + 2 * t + 8];
        a[3] = *(const unsigned*)&H[(g + 8) * 72 + k0 + 2 * t + 8];
#pragma unroll
        for (int nf = 0; nf < 8; nf++) {
            unsigned b[2];
            b[0] = *(const unsigned*)&sW2t[(nf * 8 + g) * 72 + k0 + 2 * t];
            b[1] = *(const unsigned*)&sW2t[(nf * 8 + g) * 72 + k0 + 2 * t + 8];
            mma16816(acc2[nf], a, b);
        }
    }

    // ---- dis scale + fp16 write ----
    const float d0 = g_dis[nb + g], d1 = g_dis[nb + g + 8];
    __half2* y0 = g_y_h + (size_t)(nb + g) * 32;
    __half2* y1 = g_y_h + (size_t)(nb + g + 8) * 32;
#pragma unroll
    for (int nf = 0; nf < 8; nf++) {
        const int cw = nf * 4 + t;       // (nf*8 + 2t) / 2
        y0[cw] = __floats2half2_rn(acc2[nf][0] * d0, acc2[nf][1] * d0);
        y1[cw] = __floats2half2_rn(acc2[nf][2] * d1, acc2[nf][3] * d1);
    }
}

// ---------------- gather64 + fused mean-pool partial reduction ----------------
__global__ void gather64_pool_kernel(const float* __restrict__ bias) {
    __shared__ float pool[64];
    const __half2* __restrict__ y = g_y_h;
    const int tid = threadIdx.x;
    const int gw = (blockIdx.x * 256 + tid) >> 5;
    const int lane = tid & 31;
    if (tid < 64) pool[tid] = 0.f;
    __syncthreads();

    float2 a = __half22float2(__ldg(&y[gw * 32 + lane]));
    int p = g_off[gw];
    const int e = g_off[gw + 1];
    for (; p + 8 <= e; p += 8) {
        int j0 = __ldg(&g_srcs[p + 0]), j1 = __ldg(&g_srcs[p + 1]);
        int j2 = __ldg(&g_srcs[p + 2]), j3 = __ldg(&g_srcs[p + 3]);
        int j4 = __ldg(&g_srcs[p + 4]), j5 = __ldg(&g_srcs[p + 5]);
        int j6 = __ldg(&g_srcs[p + 6]), j7 = __ldg(&g_srcs[p + 7]);
        float2 v0 = __half22float2(__ldg(&y[j0 * 32 + lane]));
        float2 v1 = __half22float2(__ldg(&y[j1 * 32 + lane]));
        float2 v2 = __half22float2(__ldg(&y[j2 * 32 + lane]));
        float2 v3 = __half22float2(__ldg(&y[j3 * 32 + lane]));
        float2 v4 = __half22float2(__ldg(&y[j4 * 32 + lane]));
        float2 v5 = __half22float2(__ldg(&y[j5 * 32 + lane]));
        float2 v6 = __half22float2(__ldg(&y[j6 * 32 + lane]));
        float2 v7 = __half22float2(__ldg(&y[j7 * 32 + lane]));
        a.x += ((v0.x + v1.x) + (v2.x + v3.x)) + ((v4.x + v5.x) + (v6.x + v7.x));
        a.y += ((v0.y + v1.y) + (v2.y + v3.y)) + ((v4.y + v5.y) + (v6.y + v7.y));
    }
    for (; p < e; p++) {
        int j = __ldg(&g_srcs[p]);
        float2 v = __half22float2(__ldg(&y[j * 32 + lane]));
        a.x += v.x; a.y += v.y;
    }
    const float d = g_dis[gw];
    float2 bb = ((const float2*)bias)[lane];
    float rx = fmaxf(fmaf(d, a.x, bb.x), 0.f);
    float ry = fmaxf(fmaf(d, a.y, bb.y), 0.f);
    atomicAdd(&pool[2 * lane],     rx);
    atomicAdd(&pool[2 * lane + 1], ry);
    __syncthreads();
    if (tid < 64) {
        const int batch = gw >> 11;
        atomicAdd(&g_pool[batch * 64 + tid], pool[tid]);
    }
}

// ---------------- classifier from pooled sums ----------------
__global__ void cls_kernel(const float* __restrict__ clsw,
                           const float* __restrict__ clsb,
                           float* __restrict__ out) {
    __shared__ float sw[64 * OUTC];
    const int tid = threadIdx.x;
    if (tid < 64 * OUTC) sw[tid] = clsw[tid];
    __syncthreads();
    if (tid < BATCH * OUTC) {
        const int b = tid / OUTC, o = tid - b * OUTC;
        float acc = clsb[o];
#pragma unroll
        for (int c = 0; c < 64; c++)
            acc += g_pool[b * 64 + c] * sw[c * OUTC + o];
        out[tid] = acc * (1.f / (float)T4) + clsb[o] * (1.f - 1.f / (float)T4);
    }
}

// ---------------- launch ----------------
extern "C" void kernel_launch(void* const* d_in, const int* in_sizes, int n_in,
                              void* d_out, int out_size) {
    const float* x       = nullptr;
    const int*   ei      = nullptr;
    const float* conv1_w = nullptr; const float* conv1_b = nullptr;
    const float* conv2_w = nullptr; const float* conv2_b = nullptr;
    const float* gcn1_w  = nullptr; const float* gcn1_b  = nullptr;
    const float* gcn2_w  = nullptr; const float* gcn2_b  = nullptr;
    const float* cls_w   = nullptr; const float* cls_b   = nullptr;

    for (int i = 0; i < n_in; i++) {
        switch (in_sizes[i]) {
            case BATCH * 16 * T_IN:   x       = (const float*)d_in[i]; break;
            case 2 * N_EDGES:         ei      = (const int*)  d_in[i]; break;
            case 16 * 16 * 5:         conv1_w = (const float*)d_in[i]; break;
            case 16:                  conv1_b = (const float*)d_in[i]; break;
            case 32 * 16 * 5:         conv2_w = (const float*)d_in[i]; break;
            case 32:                  conv2_b = (const float*)d_in[i]; break;
            case 32 * HID:            gcn1_w  = (const float*)d_in[i]; break;
            case HID * HID:           gcn2_w  = (const float*)d_in[i]; break;
            case HID * OUTC:          cls_w   = (const float*)d_in[i]; break;
            case OUTC:                cls_b   = (const float*)d_in[i]; break;
            case HID:
                if (!gcn1_b) gcn1_b = (const float*)d_in[i];
                else         gcn2_b = (const float*)d_in[i];
                break;
            default: break;
        }
    }
    if (!x || !ei || !conv1_w || !conv2_w || !gcn1_w || !gcn2_w || !cls_w) {
        x       = (const float*)d_in[0];  ei      = (const int*)  d_in[1];
        conv1_w = (const float*)d_in[2];  conv1_b = (const float*)d_in[3];
        conv2_w = (const float*)d_in[4];  conv2_b = (const float*)d_in[5];
        gcn1_w  = (const float*)d_in[6];  gcn1_b  = (const float*)d_in[7];
        gcn2_w  = (const float*)d_in[8];  gcn2_b  = (const float*)d_in[9];
        cls_w   = (const float*)d_in[10]; cls_b   = (const float*)d_in[11];
    }

    float* out = (float*)d_out;
    const int* e_row = ei;
    const int* e_col = ei + N_EDGES;

    cudaFuncSetAttribute(conv_fused_kernel,
                         cudaFuncAttributeMaxDynamicSharedMemorySize, SM_BYTES);

    static cudaStream_t s_side = nullptr;
    static cudaEvent_t  s_fork = nullptr, s_join = nullptr;
    if (!s_side) {
        cudaStreamCreateWithFlags(&s_side, cudaStreamNonBlocking);
        cudaEventCreateWithFlags(&s_fork, cudaEventDisableTiming);
        cudaEventCreateWithFlags(&s_join, cudaEventDisableTiming);
    }

    // shared prefix: counts + dis (conv needs dis; CSR tail needs counts)
    zero_cnt_kernel<<<N_NODES / 256, 256>>>();
    hist_kernel<<<N_EDGES / 256, 256>>>(e_col);
    scan1_kernel<<<128, 256>>>();

    // fork: CSR tail (scan2/scan3/place) overlaps conv_fused
    cudaEventRecord(s_fork, 0);
    cudaStreamWaitEvent(s_side, s_fork, 0);
    scan2_kernel<<<1, 128, 0, s_side>>>();
    scan3_kernel<<<N_NODES / 256, 256, 0, s_side>>>();
    place_kernel<<<N_EDGES / 256, 256, 0, s_side>>>(e_row, e_col);
    cudaEventRecord(s_join, s_side);

    {
        dim3 gc(T4 / 128, BATCH);
        conv_fused_kernel<<<gc, 256, SM_BYTES>>>(x, conv1_w, conv1_b, conv2_w, conv2_b);
    }

    cudaStreamWaitEvent(0, s_join, 0);

    gather32_kernel<<<N_NODES / 8, 256>>>();
    xw_mma_kernel<<<N_NODES / 128, 256>>>(gcn1_w, gcn1_b, gcn2_w);
    gather64_pool_kernel<<<N_NODES / 8, 256>>>(gcn2_b);
    cls_kernel<<<1, 640>>>(cls_w, cls_b, out);
}